// round 15
// baseline (speedup 1.0000x reference)
#include <cuda_runtime.h>
#include <cuda_fp16.h>
#include <math.h>

#define N 8192
#define D 32
#define NUM_ITERS 100
#define EPSF 0.1f
#define STABF 1e-8f
#define INV_N (1.0f / 8192.0f)

// fp8 e4m3 storage scale: K' = 64*K maps K in [~4e-3, 1] to [0.25, 64],
// inside e4m3 normal range [1.56e-2, 448]. Folded exactly into updates.
#define KSCALE 64.0f
#define INV_KSCALE (1.0f / 64.0f)

// ---------------------------------------------------------------------------
// Static device scratch (allocation-free). 4 x 64MB fp8 Gibbs matrices,
// declared as uint4 arrays to guarantee 16B alignment for vector loads.
// ---------------------------------------------------------------------------
__device__ uint4 g_Kst4[(size_t)N * N / 16];  // rows = source, cols = target
__device__ uint4 g_Kts4[(size_t)N * N / 16];  // transpose (recomputed, bit-identical)
__device__ uint4 g_Kss4[(size_t)N * N / 16];  // symmetric
__device__ uint4 g_Ktt4[(size_t)N * N / 16];  // symmetric
__device__ float g_u[3 * N];
__device__ float g_v[3 * N];
__device__ double g_part[3 * N];

// ---------------------------------------------------------------------------
// fp32 -> e4m3 (satfinite), single byte.
// ---------------------------------------------------------------------------
__device__ __forceinline__ unsigned char f32_to_e4m3(float f) {
    unsigned short r;
    asm("cvt.rn.satfinite.e4m3x2.f32 %0, %1, %2;" : "=h"(r) : "f"(f), "f"(f));
    return (unsigned char)r;
}

// 4 fp8 (one 32-bit word) dot 4 fp32, fp32 accumulate. e4m3->f16 is exact.
__device__ __forceinline__ float dotword(unsigned w, float4 x, float acc) {
    unsigned h0, h1;
    asm("{\n\t"
        ".reg .b16 lo, hi;\n\t"
        "mov.b32 {lo, hi}, %2;\n\t"
        "cvt.rn.f16x2.e4m3x2 %0, lo;\n\t"
        "cvt.rn.f16x2.e4m3x2 %1, hi;\n\t"
        "}"
        : "=r"(h0), "=r"(h1) : "r"(w));
    float2 f01 = __half22float2(*reinterpret_cast<__half2*>(&h0));
    float2 f23 = __half22float2(*reinterpret_cast<__half2*>(&h1));
    acc = fmaf(f01.x, x.x, acc);
    acc = fmaf(f01.y, x.y, acc);
    acc = fmaf(f23.x, x.z, acc);
    acc = fmaf(f23.y, x.w, acc);
    return acc;
}

// Unpack one fp8 word to 4 floats (true K = K'/64).
__device__ __forceinline__ float4 word_to_k(unsigned w) {
    unsigned h0, h1;
    asm("{\n\t"
        ".reg .b16 lo, hi;\n\t"
        "mov.b32 {lo, hi}, %2;\n\t"
        "cvt.rn.f16x2.e4m3x2 %0, lo;\n\t"
        "cvt.rn.f16x2.e4m3x2 %1, hi;\n\t"
        "}"
        : "=r"(h0), "=r"(h1) : "r"(w));
    float2 f01 = __half22float2(*reinterpret_cast<__half2*>(&h0));
    float2 f23 = __half22float2(*reinterpret_cast<__half2*>(&h1));
    return make_float4(f01.x * INV_KSCALE, f01.y * INV_KSCALE,
                       f23.x * INV_KSCALE, f23.y * INV_KSCALE);
}

// ---------------------------------------------------------------------------
// Init u = 1 (reference scan starts from ones; v is overwritten first).
// ---------------------------------------------------------------------------
__global__ void init_u_kernel() {
    for (int i = blockIdx.x * blockDim.x + threadIdx.x; i < 3 * N;
         i += gridDim.x * blockDim.x)
        g_u[i] = 1.0f;
}

// ---------------------------------------------------------------------------
// Build the 4 Gibbs matrices: K'[i][j] = e4m3(64 * exp(-max(...,0)/eps)).
// FMA order over k identical for Kst and Kts => bit-identical transpose.
// grid = (N/128, 4), 256 threads.
// ---------------------------------------------------------------------------
__global__ __launch_bounds__(256) void build_kernels(const float* __restrict__ src,
                                                     const float* __restrict__ tgt) {
    const int m = blockIdx.y;
    const float* A;
    const float* B;
    unsigned char* K;
    if (m == 0)      { A = src; B = tgt; K = (unsigned char*)g_Kst4; }
    else if (m == 1) { A = tgt; B = src; K = (unsigned char*)g_Kts4; }
    else if (m == 2) { A = src; B = src; K = (unsigned char*)g_Kss4; }
    else             { A = tgt; B = tgt; K = (unsigned char*)g_Ktt4; }

    __shared__ float sA[128 * D];
    __shared__ float sNA[128];
    const int rowBase = blockIdx.x * 128;

    for (int idx = threadIdx.x; idx < 128 * D; idx += 256)
        sA[idx] = A[(size_t)rowBase * D + idx];
    __syncthreads();
    for (int i = threadIdx.x; i < 128; i += 256) {
        float s = 0.f;
#pragma unroll
        for (int k = 0; k < D; k++) s = fmaf(sA[i * D + k], sA[i * D + k], s);
        sNA[i] = s;
    }
    __syncthreads();

    for (int jBase = 0; jBase < N; jBase += 256) {
        const int j = jBase + threadIdx.x;
        float bb[D];
        const float4* bp = (const float4*)(B + (size_t)j * D);
#pragma unroll
        for (int q = 0; q < D / 4; q++) {
            float4 t = bp[q];
            bb[q * 4 + 0] = t.x; bb[q * 4 + 1] = t.y;
            bb[q * 4 + 2] = t.z; bb[q * 4 + 3] = t.w;
        }
        float nb = 0.f;
#pragma unroll
        for (int k = 0; k < D; k++) nb = fmaf(bb[k], bb[k], nb);

#pragma unroll 4
        for (int i = 0; i < 128; i++) {
            float dot = 0.f;
#pragma unroll
            for (int k = 0; k < D; k++) dot = fmaf(sA[i * D + k], bb[k], dot);
            float d = sNA[i] + nb - 2.0f * dot;
            d = fmaxf(d, 0.0f);
            K[(size_t)(rowBase + i) * N + j] =
                f32_to_e4m3(expf(d * (-1.0f / EPSF)) * KSCALE);
        }
    }
}

// ---------------------------------------------------------------------------
// One Sinkhorn half-step for all 3 problems (fp8 K', fp32 x/accumulate):
//   phase 0: v = nu / (K^T u + stab)  -> stream {Kts, Kss, Ktt} rows
//   phase 1: u = mu / (K  v + stab)   -> stream {Kst, Kss, Ktt} rows
// Scale fold: acc = 64*(Kx) => y = (64/N)/(acc + 64*stab).
// x staged in 4 deinterleaved smem arrays: every LDS.128 is 16B-strided
// across lanes => zero bank conflicts (fixes R12's 8-way conflict).
// 512 threads, 2 rows/warp => 32 rows/block. grid = (N/32, 3). 192MB/launch.
// ---------------------------------------------------------------------------
__global__ __launch_bounds__(512) void half_step(int phase) {
    const int p = blockIdx.y;
    const uint4* M;
    const float* x;
    float* y;
    if (phase == 0) {
        M = (p == 0) ? g_Kts4 : (p == 1) ? g_Kss4 : g_Ktt4;
        x = g_u + p * N;
        y = g_v + p * N;
    } else {
        M = (p == 0) ? g_Kst4 : (p == 1) ? g_Kss4 : g_Ktt4;
        x = g_v + p * N;
        y = g_u + p * N;
    }

    // Deinterleaved x: slot s covers columns 16s..16s+15.
    __shared__ float4 xsA[N / 16], xsB[N / 16], xsC[N / 16], xsD[N / 16];
    {
        const float4* x4 = (const float4*)x;
        for (int j = threadIdx.x; j < N / 4; j += 512) {
            float4 f = x4[j];
            const int s = j >> 2, q = j & 3;
            if (q == 0)      xsA[s] = f;
            else if (q == 1) xsB[s] = f;
            else if (q == 2) xsC[s] = f;
            else             xsD[s] = f;
        }
    }
    __syncthreads();

    const int warp = threadIdx.x >> 5;
    const int lane = threadIdx.x & 31;
    const int row0 = blockIdx.x * 32 + warp * 2;

    const uint4* M0 = M + (size_t)row0 * (N / 16);
    const uint4* M1 = M + (size_t)(row0 + 1) * (N / 16);

    float acc0 = 0.f, acc1 = 0.f;
#pragma unroll 4
    for (int i = 0; i < 16; i++) {  // 16 iters x 16 fp8/lane/row
        const int idx = lane + i * 32;
        uint4 a = M0[idx];
        uint4 b = M1[idx];
        float4 xA = xsA[idx], xB = xsB[idx], xC = xsC[idx], xD = xsD[idx];
        acc0 = dotword(a.x, xA, acc0);
        acc1 = dotword(b.x, xA, acc1);
        acc0 = dotword(a.y, xB, acc0);
        acc1 = dotword(b.y, xB, acc1);
        acc0 = dotword(a.z, xC, acc0);
        acc1 = dotword(b.z, xC, acc1);
        acc0 = dotword(a.w, xD, acc0);
        acc1 = dotword(b.w, xD, acc1);
    }
#pragma unroll
    for (int o = 16; o > 0; o >>= 1) {
        acc0 += __shfl_xor_sync(0xffffffffu, acc0, o);
        acc1 += __shfl_xor_sync(0xffffffffu, acc1, o);
    }
    if (lane == 0) {
        // y = INV_N / (acc/64 + stab) = (INV_N*64)/(acc + 64*stab)
        y[row0]     = (INV_N * KSCALE) / (acc0 + STABF * KSCALE);
        y[row0 + 1] = (INV_N * KSCALE) / (acc1 + STABF * KSCALE);
    }
}

// ---------------------------------------------------------------------------
// Final transport cost: part[row] = u_row * sum_j K*v_j*(-eps*log K).
// K recovered from fp8 K'/64; log arg clamped so flushed K'=0 contributes
// exactly 0 (factor K=0 multiplies a finite c). One-shot kernel.
// grid = (N/16, 3), 256 threads.
// ---------------------------------------------------------------------------
__global__ __launch_bounds__(256) void cost_rows() {
    const int p = blockIdx.y;
    const uint4* M = (p == 0) ? g_Kst4 : (p == 1) ? g_Kss4 : g_Ktt4;
    const float* v = g_v + p * N;
    const float* u = g_u + p * N;

    __shared__ float4 vsA[N / 16], vsB[N / 16], vsC[N / 16], vsD[N / 16];
    {
        const float4* v4 = (const float4*)v;
        for (int j = threadIdx.x; j < N / 4; j += 256) {
            float4 f = v4[j];
            const int s = j >> 2, q = j & 3;
            if (q == 0)      vsA[s] = f;
            else if (q == 1) vsB[s] = f;
            else if (q == 2) vsC[s] = f;
            else             vsD[s] = f;
        }
    }
    __syncthreads();

    const int warp = threadIdx.x >> 5;
    const int lane = threadIdx.x & 31;

#pragma unroll
    for (int r = 0; r < 2; r++) {
        const int row = blockIdx.x * 16 + warp * 2 + r;
        const uint4* Mr = M + (size_t)row * (N / 16);
        float acc = 0.f;
        for (int i = 0; i < 16; i++) {
            const int idx = lane + i * 32;
            uint4 a = Mr[idx];
            float4 k0 = word_to_k(a.x);
            float4 k1 = word_to_k(a.y);
            float4 k2 = word_to_k(a.z);
            float4 k3 = word_to_k(a.w);
            float4 x0 = vsA[idx], x1 = vsB[idx], x2 = vsC[idx], x3 = vsD[idx];
            const float kf[16] = {k0.x, k0.y, k0.z, k0.w, k1.x, k1.y, k1.z, k1.w,
                                  k2.x, k2.y, k2.z, k2.w, k3.x, k3.y, k3.z, k3.w};
            const float xv[16] = {x0.x, x0.y, x0.z, x0.w, x1.x, x1.y, x1.z, x1.w,
                                  x2.x, x2.y, x2.z, x2.w, x3.x, x3.y, x3.z, x3.w};
#pragma unroll
            for (int q = 0; q < 16; q++) {
                float c = -EPSF * __logf(fmaxf(kf[q], 1e-30f));
                acc = fmaf(kf[q] * xv[q], c, acc);
            }
        }
        double dacc = (double)acc;
#pragma unroll
        for (int o = 16; o > 0; o >>= 1)
            dacc += __shfl_xor_sync(0xffffffffu, dacc, o);
        if (lane == 0) g_part[p * N + row] = dacc * (double)u[row];
    }
}

// ---------------------------------------------------------------------------
// Final stage 2: deterministic single-block reduction of 3x8192 partials,
// then debiased divergence / n.
// ---------------------------------------------------------------------------
__global__ __launch_bounds__(256) void final_reduce(float* __restrict__ out) {
    __shared__ double sred[3][8];
    const int warp = threadIdx.x >> 5;
    const int lane = threadIdx.x & 31;

    for (int p = 0; p < 3; p++) {
        double s = 0.0;
        for (int i = threadIdx.x; i < N; i += 256) s += g_part[p * N + i];
#pragma unroll
        for (int o = 16; o > 0; o >>= 1)
            s += __shfl_xor_sync(0xffffffffu, s, o);
        if (lane == 0) sred[p][warp] = s;
    }
    __syncthreads();
    if (threadIdx.x == 0) {
        double w[3];
        for (int p = 0; p < 3; p++) {
            double s = 0.0;
            for (int q = 0; q < 8; q++) s += sred[p][q];
            w[p] = s;
        }
        double cost = w[0] - 0.5 * w[1] - 0.5 * w[2];
        out[0] = (float)(cost / (double)N);
    }
}

// ---------------------------------------------------------------------------
// kernel_launch: pure kernel launches, graph-capturable, allocation-free.
// ---------------------------------------------------------------------------
extern "C" void kernel_launch(void* const* d_in, const int* in_sizes, int n_in,
                              void* d_out, int out_size) {
    const float* src = (const float*)d_in[0];
    const float* tgt = (const float*)d_in[1];
    float* out = (float*)d_out;

    init_u_kernel<<<24, 256>>>();
    build_kernels<<<dim3(N / 128, 4), 256>>>(src, tgt);

    for (int t = 0; t < NUM_ITERS; t++) {
        half_step<<<dim3(N / 32, 3), 512>>>(0);
        half_step<<<dim3(N / 32, 3), 512>>>(1);
    }

    cost_rows<<<dim3(N / 16, 3), 256>>>();
    final_reduce<<<1, 256>>>(out);
}